// round 1
// baseline (speedup 1.0000x reference)
#include <cuda_runtime.h>

#define STRIDE   10
#define NF       128
#define PAIRS    8128      // 128*127/2
#define NTILES   528       // 32*33/2 lower-tri 4x4 block tiles (incl. diagonal)
#define THREADS  256

__global__ __launch_bounds__(THREADS)
void corr_win_kernel(const float* __restrict__ x, float* __restrict__ out)
{
    __shared__ float ms[STRIDE][NF];   // centered window, s-major
    __shared__ float inv[NF];          // 1/||ms_f|| (0 if zero variance)
    __shared__ float stage[PAIRS];     // staged lower-tri correlations

    const int w   = blockIdx.x;                       // window = b*100 + l
    const int tid = threadIdx.x;
    const float* __restrict__ xw = x + (size_t)w * (STRIDE * NF); // windows contiguous

    // ---- Phase 1: coalesced load of 1280 floats -------------------------
    #pragma unroll
    for (int k = 0; k < (STRIDE * NF) / THREADS; ++k) {
        int idx = tid + k * THREADS;
        ms[idx / NF][idx % NF] = xw[idx];
    }
    __syncthreads();

    // ---- Phase 2: per-feature center + inverse norm ---------------------
    if (tid < NF) {
        float sum = 0.f;
        #pragma unroll
        for (int s = 0; s < STRIDE; ++s) sum += ms[s][tid];
        float mean = sum * (1.0f / STRIDE);
        float s2 = 0.f;
        #pragma unroll
        for (int s = 0; s < STRIDE; ++s) {
            float v = ms[s][tid] - mean;
            ms[s][tid] = v;
            s2 = fmaf(v, v, s2);
        }
        inv[tid] = (s2 > 0.f) ? rsqrtf(s2) : 0.f;
    }
    __syncthreads();

    // ---- Phase 3: 4x4 register-tiled pair dot products ------------------
    for (int t = tid; t < NTILES; t += THREADS) {
        // invert triangular tile index: t = bi*(bi+1)/2 + bj, bj <= bi
        int bi = (int)((sqrtf(8.f * (float)t + 1.f) - 1.f) * 0.5f);
        while ((bi + 1) * (bi + 2) / 2 <= t) ++bi;
        while (bi * (bi + 1) / 2 > t) --bi;
        int bj = t - bi * (bi + 1) / 2;
        int i0 = bi * 4, j0 = bj * 4;

        float acc[4][4] = {};
        #pragma unroll
        for (int s = 0; s < STRIDE; ++s) {
            float4 a4 = *(const float4*)&ms[s][i0];
            float4 b4 = *(const float4*)&ms[s][j0];
            float av[4] = {a4.x, a4.y, a4.z, a4.w};
            float bv[4] = {b4.x, b4.y, b4.z, b4.w};
            #pragma unroll
            for (int u = 0; u < 4; ++u)
                #pragma unroll
                for (int v = 0; v < 4; ++v)
                    acc[u][v] = fmaf(av[u], bv[v], acc[u][v]);
        }

        #pragma unroll
        for (int u = 0; u < 4; ++u) {
            int i = i0 + u;
            float ci = inv[i];
            int pbase = (i * (i - 1)) / 2 + j0;   // row-major strict-lower-tri offset
            #pragma unroll
            for (int v = 0; v < 4; ++v) {
                int j = j0 + v;
                if (j < i)
                    stage[pbase + v] = acc[u][v] * ci * inv[j];
            }
        }
    }
    __syncthreads();

    // ---- Phase 4: coalesced float4 writeback ----------------------------
    float4* __restrict__ o4 = (float4*)(out + (size_t)w * PAIRS);
    const float4* s4 = (const float4*)stage;
    #pragma unroll 4
    for (int k = tid; k < PAIRS / 4; k += THREADS)
        o4[k] = s4[k];
}

extern "C" void kernel_launch(void* const* d_in, const int* in_sizes, int n_in,
                              void* d_out, int out_size)
{
    const float* x  = (const float*)d_in[0];
    float* out      = (float*)d_out;
    int n_windows   = in_sizes[0] / (STRIDE * NF);   // 64*1000*128 / 1280 = 6400
    corr_win_kernel<<<n_windows, THREADS>>>(x, out);
}

// round 2
// speedup vs baseline: 1.0993x; 1.0993x over previous
#include <cuda_runtime.h>

#define STRIDE   10
#define NF       128
#define PAIRS    8128      // 128*127/2
#define NTILES   136       // 16*17/2 lower-tri 8x8 block tiles (incl. diagonal)
#define THREADS  160

__global__ __launch_bounds__(THREADS)
void corr_win_kernel(const float* __restrict__ x, float* __restrict__ out)
{
    __shared__ float ms[STRIDE][NF];   // centered, pre-scaled columns (x-mean)/||x-mean||
    __shared__ float stage[PAIRS];     // staged lower-tri correlations

    const int w   = blockIdx.x;                       // window = b*100 + l
    const int tid = threadIdx.x;
    const float* __restrict__ xw = x + (size_t)w * (STRIDE * NF);

    // ---- Phase 1+2 fused: load column, center, scale, one STS pass ------
    if (tid < NF) {
        float v[STRIDE];
        #pragma unroll
        for (int s = 0; s < STRIDE; ++s) v[s] = xw[s * NF + tid];  // coalesced per s
        float sum = 0.f;
        #pragma unroll
        for (int s = 0; s < STRIDE; ++s) sum += v[s];
        float mean = sum * (1.0f / STRIDE);
        float s2 = 0.f;
        #pragma unroll
        for (int s = 0; s < STRIDE; ++s) {
            v[s] -= mean;
            s2 = fmaf(v[s], v[s], s2);
        }
        float invn = (s2 > 0.f) ? rsqrtf(s2) : 0.f;    // divide_no_nan: 0 -> zero column
        #pragma unroll
        for (int s = 0; s < STRIDE; ++s) ms[s][tid] = v[s] * invn;
    }
    __syncthreads();

    // ---- Phase 3: one 8x8 register tile per thread -----------------------
    if (tid < NTILES) {
        // invert triangular tile index: tid = bi*(bi+1)/2 + bj, bj <= bi
        int bi = (int)((sqrtf(8.f * (float)tid + 1.f) - 1.f) * 0.5f);
        while ((bi + 1) * (bi + 2) / 2 <= tid) ++bi;
        while (bi * (bi + 1) / 2 > tid) --bi;
        const int bj = tid - bi * (bi + 1) / 2;
        const int i0 = bi * 8, j0 = bj * 8;

        float acc[8][8] = {};
        #pragma unroll
        for (int s = 0; s < STRIDE; ++s) {
            float4 a0 = *(const float4*)&ms[s][i0];
            float4 a1 = *(const float4*)&ms[s][i0 + 4];
            float4 b0 = *(const float4*)&ms[s][j0];
            float4 b1 = *(const float4*)&ms[s][j0 + 4];
            float av[8] = {a0.x, a0.y, a0.z, a0.w, a1.x, a1.y, a1.z, a1.w};
            float bv[8] = {b0.x, b0.y, b0.z, b0.w, b1.x, b1.y, b1.z, b1.w};
            #pragma unroll
            for (int u = 0; u < 8; ++u)
                #pragma unroll
                for (int vv = 0; vv < 8; ++vv)
                    acc[u][vv] = fmaf(av[u], bv[vv], acc[u][vv]);
        }

        if (bi != bj) {
            // fully valid off-diagonal tile: all 64 outputs
            #pragma unroll
            for (int u = 0; u < 8; ++u) {
                const int i  = i0 + u;
                const int pb = (i * (i - 1)) / 2 + j0;  // strict-lower-tri row base
                #pragma unroll
                for (int vv = 0; vv < 8; ++vv)
                    stage[pb + vv] = acc[u][vv];
            }
        } else {
            // diagonal tile: only j < i valid
            #pragma unroll
            for (int u = 1; u < 8; ++u) {
                const int i  = i0 + u;
                const int pb = (i * (i - 1)) / 2 + j0;
                #pragma unroll
                for (int vv = 0; vv < 8; ++vv)
                    if (vv < u) stage[pb + vv] = acc[u][vv];
            }
        }
    }
    __syncthreads();

    // ---- Phase 4: coalesced float4 writeback ----------------------------
    float4* __restrict__ o4 = (float4*)(out + (size_t)w * PAIRS);
    const float4* s4 = (const float4*)stage;
    for (int k = tid; k < PAIRS / 4; k += THREADS)
        o4[k] = s4[k];
}

extern "C" void kernel_launch(void* const* d_in, const int* in_sizes, int n_in,
                              void* d_out, int out_size)
{
    const float* x = (const float*)d_in[0];
    float* out     = (float*)d_out;
    int n_windows  = in_sizes[0] / (STRIDE * NF);   // 6400
    corr_win_kernel<<<n_windows, THREADS>>>(x, out);
}

// round 3
// speedup vs baseline: 1.6200x; 1.4737x over previous
#include <cuda_runtime.h>

#define STRIDE   10
#define NF       128
#define PAIRS    8128      // 128*127/2
#define NTASKS   20        // warp tiles: 8 row-blocks of 16 x ceil((i0+16)/32) j-chunks
#define THREADS  320       // 10 warps x 2 tasks each

// task -> (row-block, j-chunk) tables
__constant__ unsigned char c_bi8[NTASKS] = {0,1,2,2,3,3,4,4,4,5,5,5,6,6,6,6,7,7,7,7};
__constant__ unsigned char c_jc [NTASKS] = {0,0,0,1,0,1,0,1,2,0,1,2,0,1,2,3,0,1,2,3};

__global__ __launch_bounds__(THREADS)
void corr_win_kernel(const float* __restrict__ x, float* __restrict__ out)
{
    __shared__ float ms[STRIDE][NF];   // normalized columns: (x-mean)/||x-mean||

    const int w    = blockIdx.x;       // window = b*100 + l
    const int tid  = threadIdx.x;
    const int warp = tid >> 5;
    const int lane = tid & 31;
    const float* __restrict__ xw = x + (size_t)w * (STRIDE * NF);

    // ---- Phase 1: load column, center, scale by 1/||.||, store to smem ---
    if (tid < NF) {
        float v[STRIDE];
        #pragma unroll
        for (int s = 0; s < STRIDE; ++s) v[s] = __ldcs(&xw[s * NF + tid]);
        float sum = 0.f;
        #pragma unroll
        for (int s = 0; s < STRIDE; ++s) sum += v[s];
        const float mean = sum * (1.0f / STRIDE);
        float s2 = 0.f;
        #pragma unroll
        for (int s = 0; s < STRIDE; ++s) {
            v[s] -= mean;
            s2 = fmaf(v[s], v[s], s2);
        }
        const float invn = (s2 > 0.f) ? rsqrtf(s2) : 0.f;  // divide_no_nan
        #pragma unroll
        for (int s = 0; s < STRIDE; ++s) ms[s][tid] = v[s] * invn;
    }
    __syncthreads();

    float* __restrict__ ow = out + (size_t)w * PAIRS;

    // ---- Phase 2: two warp-tasks per warp, 16x32 tile each ---------------
    #pragma unroll
    for (int k = 0; k < 2; ++k) {
        const int t  = warp * 2 + k;
        const int i0 = (int)c_bi8[t] * 16;
        const int j  = (int)c_jc[t] * 32 + lane;

        float acc[16];
        #pragma unroll
        for (int u = 0; u < 16; ++u) acc[u] = 0.f;

        #pragma unroll
        for (int s = 0; s < STRIDE; ++s) {
            // A rows: broadcast loads (all lanes same address)
            const float4 A0 = *(const float4*)&ms[s][i0];
            const float4 A1 = *(const float4*)&ms[s][i0 + 4];
            const float4 A2 = *(const float4*)&ms[s][i0 + 8];
            const float4 A3 = *(const float4*)&ms[s][i0 + 12];
            // B column element: coalesced load (lane-consecutive)
            const float b = ms[s][j];

            acc[ 0] = fmaf(A0.x, b, acc[ 0]);
            acc[ 1] = fmaf(A0.y, b, acc[ 1]);
            acc[ 2] = fmaf(A0.z, b, acc[ 2]);
            acc[ 3] = fmaf(A0.w, b, acc[ 3]);
            acc[ 4] = fmaf(A1.x, b, acc[ 4]);
            acc[ 5] = fmaf(A1.y, b, acc[ 5]);
            acc[ 6] = fmaf(A1.z, b, acc[ 6]);
            acc[ 7] = fmaf(A1.w, b, acc[ 7]);
            acc[ 8] = fmaf(A2.x, b, acc[ 8]);
            acc[ 9] = fmaf(A2.y, b, acc[ 9]);
            acc[10] = fmaf(A2.z, b, acc[10]);
            acc[11] = fmaf(A2.w, b, acc[11]);
            acc[12] = fmaf(A3.x, b, acc[12]);
            acc[13] = fmaf(A3.y, b, acc[13]);
            acc[14] = fmaf(A3.z, b, acc[14]);
            acc[15] = fmaf(A3.w, b, acc[15]);
        }

        // Direct coalesced stores: row i occupies consecutive tri indices
        #pragma unroll
        for (int u = 0; u < 16; ++u) {
            const int i = i0 + u;
            if (j < i)
                __stcs(&ow[(i * (i - 1)) / 2 + j], acc[u]);
        }
    }
}

extern "C" void kernel_launch(void* const* d_in, const int* in_sizes, int n_in,
                              void* d_out, int out_size)
{
    const float* x = (const float*)d_in[0];
    float* out     = (float*)d_out;
    int n_windows  = in_sizes[0] / (STRIDE * NF);   // 6400
    corr_win_kernel<<<n_windows, THREADS>>>(x, out);
}